// round 2
// baseline (speedup 1.0000x reference)
#include <cuda_runtime.h>

#define NSTEP 51200
#define BATCH 512
#define CHUNK 512
#define NCHUNK (NSTEP / CHUNK)

// ---------------- scratch (static device arrays; no allocation) ----------------
__device__ float g_xproj[NSTEP * 40];
__device__ float g_hseq [NSTEP * 10];
__device__ float g_xin1 [NSTEP * 20];
__device__ float g_hl   [NSTEP * 60];
__device__ float g_c    [NSTEP * 20];
__device__ float g_s4   [NSTEP * 20];
__device__ float g_out1 [NSTEP * 20];
__device__ float g_out2 [NSTEP * 10];
__device__ float g_sfin [NSTEP * 10];
__device__ float g_fused[BATCH * 200];
__device__ float g_part [BATCH * 2];
__device__ float g_stats[3];
__device__ int   g_prog;          // LSTM chunk progress counter

// ---------------- K1: LSTM input projection (parallel) + flag reset ----------------
__global__ void k_xproj(const float* __restrict__ x, const float* __restrict__ wih,
                        const float* __restrict__ bih, const float* __restrict__ bhh) {
    __shared__ float xs[64 * 100];
    __shared__ float ws[40 * 65];
    __shared__ float bs[40];
    int b = blockIdx.x, tid = threadIdx.x;
    if (b == 0 && tid == 0) g_prog = 0;            // reset pipeline flag each run
    const float* xg = x + b * 6400;
    for (int i = tid; i < 6400; i += 256) xs[i] = xg[i];
    for (int i = tid; i < 2560; i += 256) ws[(i >> 6) * 65 + (i & 63)] = wih[i];
    if (tid < 40) bs[tid] = bih[tid] + bhh[tid];
    __syncthreads();
    for (int i = tid; i < 4000; i += 256) {
        int tp = i / 40, j = i % 40;
        float acc = bs[j];
        #pragma unroll
        for (int c0 = 0; c0 < 64; c0++)
            acc = fmaf(xs[c0 * 100 + tp], ws[j * 65 + c0], acc);
        g_xproj[(b * 100 + tp) * 40 + j] = acc;
    }
}

// ---------------- LIF chunk scan helper (12-cyc chain, 16-deep prefetch) ----------
__device__ __forceinline__ void lif_chunk(const float* __restrict__ in, int sin, int iin,
                                          float* __restrict__ out, int sout, int iout,
                                          float& v, float invt, float om, float th, int t0) {
    const float* ip = in + (size_t)t0 * sin + iin;
    float* op = out + (size_t)t0 * sout + iout;
    float xr[16];
    #pragma unroll
    for (int u = 0; u < 16; u++) xr[u] = fmaf(ip[u * sin], invt, -th);
    for (int tb = 0; tb < CHUNK; tb += 16) {
        #pragma unroll
        for (int u = 0; u < 16; u++) {
            int tt = tb + u;
            float d = fmaf(v, om, xr[u]);              // d = v_new - theta
            int np = tt + 16;
            float nx = (np < CHUNK) ? ip[(size_t)np * sin] : 0.f;
            xr[u] = fmaf(nx, invt, -th);
            int msk = __float_as_int(d) >> 31;          // all-ones if keep (d<0)
            op[(size_t)tt * sout] = __int_as_float(~msk & 0x3f800000);
            v = __int_as_float(__float_as_int(d + th) & msk);
        }
    }
}

// ---------------- conv chunk: c[t,o] = hl[t,:60] . cw[o,:60] + cb[o] ----------------
__device__ __forceinline__ void conv_chunk(const float* __restrict__ cw,
                                           const float* __restrict__ cb, int t0, int tid) {
    for (int rr = tid; rr < CHUNK; rr += 256) {
        float acc[20];
        #pragma unroll
        for (int o = 0; o < 20; o++) acc[o] = cb[o];
        const float4* hrow = (const float4*)(g_hl + (size_t)(t0 + rr) * 60);
        #pragma unroll
        for (int mb = 0; mb < 15; mb++) {
            float4 hv = hrow[mb];
            #pragma unroll
            for (int o = 0; o < 20; o++) {
                const float4 wv = *(const float4*)(cw + o * 60 + mb * 4);
                acc[o] = fmaf(hv.x, wv.x, acc[o]);
                acc[o] = fmaf(hv.y, wv.y, acc[o]);
                acc[o] = fmaf(hv.z, wv.z, acc[o]);
                acc[o] = fmaf(hv.w, wv.w, acc[o]);
            }
        }
        float* crow = g_c + (size_t)(t0 + rr) * 20;
        #pragma unroll
        for (int o = 0; o < 20; o++) crow[o] = acc[o];
    }
}

// ---------------- fc + skip chunk ----------------
template <int FOUT>
__device__ __forceinline__ void fcskip_chunk(const float* __restrict__ fw, const float* __restrict__ fb,
                                             const float* __restrict__ skw, const float* __restrict__ skb,
                                             const float* __restrict__ xin, float* __restrict__ outp,
                                             int t0, int tid) {
    for (int rr = tid; rr < CHUNK; rr += 256) {
        float acc[FOUT];
        #pragma unroll
        for (int o = 0; o < FOUT; o++) acc[o] = fb[o] + skb[o];
        const float* srow = g_s4 + (size_t)(t0 + rr) * 20;
        const float* xrow = xin + (size_t)(t0 + rr) * 20;
        #pragma unroll
        for (int m = 0; m < 20; m++) {
            float sm = srow[m], xm = xrow[m];
            #pragma unroll
            for (int o = 0; o < FOUT; o++)
                acc[o] = fmaf(sm, fw[o * 20 + m], fmaf(xm, skw[o * 20 + m], acc[o]));
        }
        float* orow = outp + (size_t)(t0 + rr) * FOUT;
        #pragma unroll
        for (int o = 0; o < FOUT; o++) orow[o] = acc[o];
    }
}

// ---------------- K2: persistent pipeline: block0 = LSTM warp, block1 = consumer ----
__global__ void __launch_bounds__(256, 1)
k_pipeline(const float* __restrict__ whh,
           const float* __restrict__ scw, const float* __restrict__ scb,
           const float* __restrict__ c1w, const float* __restrict__ c1b,
           const float* __restrict__ f1w, const float* __restrict__ f1b,
           const float* __restrict__ s1w, const float* __restrict__ s1b,
           const float* __restrict__ c2w, const float* __restrict__ c2b,
           const float* __restrict__ f2w, const float* __restrict__ f2b,
           const float* __restrict__ s2w, const float* __restrict__ s2b) {
    __shared__ float sh_h[CHUNK * 10];
    __shared__ __align__(16) float s_c1w[1200];
    __shared__ __align__(16) float s_c2w[1200];
    __shared__ float s_scw[200], s_scb[20], s_c1b[20], s_c2b[20];
    __shared__ float s_f1w[400], s_f1b[20], s_s1w[400], s_s1b[20];
    __shared__ float s_f2w[200], s_f2b[10], s_s2w[200], s_s2b[10];

    if (blockIdx.x == 0) {
        // ---------------- producer: serial LSTM scan, single warp ----------------
        if (threadIdx.x >= 32) return;
        const int lane = threadIdx.x;
        // lanes 0-9: gate i rows 0-9; 10-19: f rows 10-19; 20-29: o rows 30-39
        const int rowA = (lane < 20) ? lane : ((lane < 30) ? lane + 10 : 30);
        const int rowB = (lane < 10) ? lane + 20 : 20;   // g rows 20-29 (lanes 0-9)
        float wA[10], wB[10];
        #pragma unroll
        for (int m = 0; m < 10; m++) { wA[m] = whh[rowA * 10 + m]; wB[m] = whh[rowB * 10 + m]; }
        float h[10];
        #pragma unroll
        for (int m = 0; m < 10; m++) h[m] = 0.f;
        float c = 0.f;
        const float* xp = g_xproj;
        float A  = xp[rowA],      Ab = xp[rowB];
        float B  = xp[40 + rowA], Bb = xp[40 + rowB];
        int t = 0;

#define LSTEP(AV, BV) {                                                        \
        float a = AV, b = BV;                                                  \
        int tp = t + 2; if (tp > NSTEP - 1) tp = NSTEP - 1;                    \
        const float* pp = xp + tp * 40;                                        \
        AV = pp[rowA]; BV = pp[rowB];                                          \
        _Pragma("unroll")                                                      \
        for (int m = 0; m < 10; m++) {                                         \
            a = fmaf(wA[m], h[m], a); b = fmaf(wB[m], h[m], b); }              \
        float s  = __fdividef(1.f, 1.f + __expf(-a));                          \
        float tb = __fdividef(2.f, 1.f + __expf(-2.f * b)) - 1.f;              \
        float sf = __shfl_sync(0xffffffffu, s, lane + 10);                     \
        float so = __shfl_sync(0xffffffffu, s, lane + 20);                     \
        c = fmaf(sf, c, s * tb);                                               \
        float tc = __fdividef(2.f, 1.f + __expf(-2.f * c)) - 1.f;              \
        float hk = so * tc;                                                    \
        if (lane < 10) g_hseq[t * 10 + lane] = hk;                             \
        _Pragma("unroll")                                                      \
        for (int m = 0; m < 10; m++) h[m] = __shfl_sync(0xffffffffu, hk, m);   \
        t++; }

        for (int ch = 0; ch < NCHUNK; ch++) {
            for (int it = 0; it < CHUNK / 2; it++) { LSTEP(A, Ab); LSTEP(B, Bb); }
            __threadfence();
            if (lane == 0) atomicExch(&g_prog, ch + 1);
        }
#undef LSTEP
        return;
    }

    // ---------------- consumer: everything downstream, chunk-pipelined ----------------
    const int tid = threadIdx.x;
    for (int i = tid; i < 200;  i += 256) s_scw[i] = scw[i];
    for (int i = tid; i < 1200; i += 256) s_c1w[i] = c1w[i];
    for (int i = tid; i < 1200; i += 256) s_c2w[i] = c2w[i];
    for (int i = tid; i < 400;  i += 256) s_f1w[i] = f1w[i];
    for (int i = tid; i < 400;  i += 256) s_s1w[i] = s1w[i];
    for (int i = tid; i < 200;  i += 256) s_f2w[i] = f2w[i];
    for (int i = tid; i < 200;  i += 256) s_s2w[i] = s2w[i];
    if (tid < 20) { s_scb[tid] = scb[tid]; s_c1b[tid] = c1b[tid]; s_c2b[tid] = c2b[tid];
                    s_f1b0: ; s_f1b[tid] = f1b[tid]; s_s1b[tid] = s1b[tid]; }
    if (tid < 10) { s_f2b[tid] = f2b[tid]; s_s2b[tid] = s2b[tid]; }
    __syncthreads();

    // persistent LIF states
    int lkk = (tid < 60) ? tid / 20 : 0;
    int lf  = (tid < 60) ? tid % 20 : 0;
    float tau3 = (lkk == 0) ? 1.2231301601484298f
               : (lkk == 1) ? 1.3678794411714423f : 1.4493289641172216f;
    float th3 = (lkk == 0) ? 0.14f : (lkk == 1) ? 0.08f : 0.06f;
    float inv3 = 1.0f / tau3, om3 = 1.0f - inv3;
    const float inv4 = 1.0f / 1.3678794411714423f, om4 = 1.0f - inv4, th4 = 0.08f;
    float v31 = 0.f, v32 = 0.f, v41 = 0.f, v42 = 0.f;

    for (int ch = 0; ch < NCHUNK; ch++) {
        if (tid == 0) { while (atomicAdd(&g_prog, 0) < ch + 1) { } }
        __syncthreads();
        const int t0 = ch * CHUNK;

        // stage hseq chunk (cross-block data: L2 via ldcg)
        for (int i = tid; i < CHUNK * 10; i += 256)
            sh_h[i] = __ldcg(&g_hseq[(size_t)t0 * 10 + i]);
        __syncthreads();

        // sc matmul -> g_xin1
        for (int rr = tid; rr < CHUNK; rr += 256) {
            float acc[20];
            #pragma unroll
            for (int o = 0; o < 20; o++) acc[o] = s_scb[o];
            #pragma unroll
            for (int m = 0; m < 10; m++) {
                float hm = sh_h[rr * 10 + m];
                #pragma unroll
                for (int o = 0; o < 20; o++) acc[o] = fmaf(hm, s_scw[o * 10 + m], acc[o]);
            }
            float* xrow = g_xin1 + (size_t)(t0 + rr) * 20;
            #pragma unroll
            for (int o = 0; o < 20; o++) xrow[o] = acc[o];
        }
        __syncthreads();

        // hr module 1
        if (tid < 60) lif_chunk(g_xin1, 20, lf, g_hl, 60, lf * 3 + lkk, v31, inv3, om3, th3, t0);
        __syncthreads();
        conv_chunk(s_c1w, s_c1b, t0, tid);
        __syncthreads();
        if (tid < 20) lif_chunk(g_c, 20, tid, g_s4, 20, tid, v41, inv4, om4, th4, t0);
        __syncthreads();
        fcskip_chunk<20>(s_f1w, s_f1b, s_s1w, s_s1b, g_xin1, g_out1, t0, tid);
        __syncthreads();

        // hr module 2
        if (tid < 60) lif_chunk(g_out1, 20, lf, g_hl, 60, lf * 3 + lkk, v32, inv3, om3, th3, t0);
        __syncthreads();
        conv_chunk(s_c2w, s_c2b, t0, tid);
        __syncthreads();
        if (tid < 20) lif_chunk(g_c, 20, tid, g_s4, 20, tid, v42, inv4, om4, th4, t0);
        __syncthreads();
        fcskip_chunk<10>(s_f2w, s_f2b, s_s2w, s_s2b, g_out1, g_out2, t0, tid);
        __syncthreads();
    }
}

// ---------------- K3: final LIF over batch axis ----------------
__global__ void k_liff() {
    int idx = threadIdx.x;
    if (idx >= 1000) return;
    const float invt = 1.0f / 1.3678794411714423f;
    const float om = 1.0f - invt, th = 0.08f;
    float v = 0.f;
    float xr[8];
    #pragma unroll
    for (int i = 0; i < 8; i++) xr[i] = fmaf(g_out2[i * 1000 + idx], invt, -th);
    for (int b = 0; b < BATCH; b += 8) {
        #pragma unroll
        for (int u = 0; u < 8; u++) {
            float d = fmaf(v, om, xr[u]);
            int nb = b + u + 8;
            float nx = (nb < BATCH) ? g_out2[nb * 1000 + idx] : 0.f;
            xr[u] = fmaf(nx, invt, -th);
            int msk = __float_as_int(d) >> 31;
            g_sfin[(b + u) * 1000 + idx] = __int_as_float(~msk & 0x3f800000);
            v = __int_as_float(__float_as_int(d + th) & msk);
        }
    }
}

// ---------------- K4: dp / avg / fused + per-batch partial sums ----------------
__global__ void k_fused() {
    int b = blockIdx.x, m = threadIdx.x;
    float dp[10];
    float s1 = 0.f, s2 = 0.f;
    if (m < 20) {
        const float* sb = g_sfin + b * 1000;
        float avgm = 0.f;
        #pragma unroll
        for (int j = 0; j < 10; j++) {
            float a = sb[(5 * m + 3) * 10 + j] + sb[(5 * m + 4) * 10 + j]
                    - sb[(5 * m + 0) * 10 + j] - sb[(5 * m + 1) * 10 + j];
            dp[j] = 0.5f * a;
            avgm += dp[j];
        }
        avgm *= 0.1f;
        #pragma unroll
        for (int j = 0; j < 10; j++) {
            float fv = dp[j] * avgm;
            g_fused[b * 200 + j * 20 + m] = fv;
            s1 += fv; s2 += fv * fv;
        }
    }
    #pragma unroll
    for (int off = 16; off; off >>= 1) {
        s1 += __shfl_xor_sync(0xffffffffu, s1, off);
        s2 += __shfl_xor_sync(0xffffffffu, s2, off);
    }
    if (m == 0) { g_part[b * 2] = s1; g_part[b * 2 + 1] = s2; }
}

// ---------------- K5: global mean/var ----------------
__global__ void k_stats(const float* __restrict__ gamma, const float* __restrict__ beta) {
    int l = threadIdx.x;
    float s1 = 0.f, s2 = 0.f;
    for (int i = l; i < BATCH; i += 32) { s1 += g_part[2 * i]; s2 += g_part[2 * i + 1]; }
    #pragma unroll
    for (int off = 16; off; off >>= 1) {
        s1 += __shfl_xor_sync(0xffffffffu, s1, off);
        s2 += __shfl_xor_sync(0xffffffffu, s2, off);
    }
    if (l == 0) {
        float n = (float)(BATCH * 200);
        float mean = s1 / n;
        float var = s2 / n - mean * mean;
        float rstd = 1.f / sqrtf(var + 1e-5f);
        g_stats[0] = mean; g_stats[1] = rstd * gamma[0]; g_stats[2] = beta[0];
    }
}

// ---------------- K6: BN + classifier + log_softmax ----------------
__global__ void k_logits(const float* __restrict__ clsw, const float* __restrict__ clsb,
                         float* __restrict__ out) {
    int b = blockIdx.x, l = threadIdx.x;
    float mean = g_stats[0], ga = g_stats[1], be = g_stats[2];
    float a0 = 0.f, a1 = 0.f, a2 = 0.f;
    for (int n = l; n < 200; n += 32) {
        float bn = (g_fused[b * 200 + n] - mean) * ga + be;
        a0 = fmaf(bn, clsw[n], a0);
        a1 = fmaf(bn, clsw[200 + n], a1);
        a2 = fmaf(bn, clsw[400 + n], a2);
    }
    #pragma unroll
    for (int off = 16; off; off >>= 1) {
        a0 += __shfl_xor_sync(0xffffffffu, a0, off);
        a1 += __shfl_xor_sync(0xffffffffu, a1, off);
        a2 += __shfl_xor_sync(0xffffffffu, a2, off);
    }
    if (l == 0) {
        float l0 = a0 + clsb[0], l1 = a1 + clsb[1], l2 = a2 + clsb[2];
        float mx = fmaxf(l0, fmaxf(l1, l2));
        float e0 = expf(l0 - mx), e1 = expf(l1 - mx), e2 = expf(l2 - mx);
        float lse = logf(e0 + e1 + e2) + mx;
        out[b * 3 + 0] = l0 - lse;
        out[b * 3 + 1] = l1 - lse;
        out[b * 3 + 2] = l2 - lse;
    }
}

// ---------------- launch ----------------
extern "C" void kernel_launch(void* const* d_in, const int* in_sizes, int n_in,
                              void* d_out, int out_size) {
    const float* x   = (const float*)d_in[0];
    const float* wih = (const float*)d_in[1];
    const float* whh = (const float*)d_in[2];
    const float* bih = (const float*)d_in[3];
    const float* bhh = (const float*)d_in[4];
    const float* scw = (const float*)d_in[5];
    const float* scb = (const float*)d_in[6];
    const float* c1w = (const float*)d_in[7];
    const float* c1b = (const float*)d_in[8];
    const float* f1w = (const float*)d_in[9];
    const float* f1b = (const float*)d_in[10];
    const float* s1w = (const float*)d_in[11];
    const float* s1b = (const float*)d_in[12];
    const float* c2w = (const float*)d_in[13];
    const float* c2b = (const float*)d_in[14];
    const float* f2w = (const float*)d_in[15];
    const float* f2b = (const float*)d_in[16];
    const float* s2w = (const float*)d_in[17];
    const float* s2b = (const float*)d_in[18];
    const float* gam = (const float*)d_in[19];
    const float* bet = (const float*)d_in[20];
    const float* clw = (const float*)d_in[21];
    const float* clb = (const float*)d_in[22];
    float* out = (float*)d_out;

    k_xproj   <<<512, 256>>>(x, wih, bih, bhh);
    k_pipeline<<<2, 256>>>(whh, scw, scb, c1w, c1b, f1w, f1b, s1w, s1b,
                           c2w, c2b, f2w, f2b, s2w, s2b);
    k_liff    <<<1, 1024>>>();
    k_fused   <<<512, 32>>>();
    k_stats   <<<1, 32>>>(gam, bet);
    k_logits  <<<512, 32>>>(clw, clb, out);
}

// round 3
// speedup vs baseline: 46.6994x; 46.6994x over previous
#include <cuda_runtime.h>

#define NSTEP 51200
#define BATCH 512
#define CHL   512          // LSTM chunk (kept steps)
#define LEADL 128          // LSTM lead-in
#define NCHL  (NSTEP / CHL)
#define CHF   512          // LIF chunk
#define LEADF 48           // LIF lead-in
#define NCHF  (NSTEP / CHF)

// ---------------- scratch (static device arrays; no allocation) ----------------
__device__ float g_xproj[NSTEP * 40];
__device__ float g_hseq [NSTEP * 10];
__device__ float g_xin1 [NSTEP * 20];
__device__ float g_hl   [NSTEP * 60];
__device__ float g_c    [NSTEP * 20];
__device__ float g_s4   [NSTEP * 20];
__device__ float g_out1 [NSTEP * 20];
__device__ float g_out2 [NSTEP * 10];
__device__ float g_sfin [NSTEP * 10];
__device__ float g_fused[BATCH * 200];
__device__ float g_part [BATCH * 2];
__device__ float g_stats[3];

__device__ __forceinline__ float sigf(float x)  { return __fdividef(1.f, 1.f + __expf(-x)); }
__device__ __forceinline__ float tfast(float x) { return __fdividef(2.f, 1.f + __expf(-2.f * x)) - 1.f; }

// ---------------- K1: LSTM input projection (fully parallel) ----------------
__global__ void k_xproj(const float* __restrict__ x, const float* __restrict__ wih,
                        const float* __restrict__ bih, const float* __restrict__ bhh) {
    __shared__ float xs[64 * 100];
    __shared__ float ws[40 * 65];
    __shared__ float bs[40];
    int b = blockIdx.x, tid = threadIdx.x;
    const float* xg = x + b * 6400;
    for (int i = tid; i < 6400; i += 256) xs[i] = xg[i];
    for (int i = tid; i < 2560; i += 256) ws[(i >> 6) * 65 + (i & 63)] = wih[i];
    if (tid < 40) bs[tid] = bih[tid] + bhh[tid];
    __syncthreads();
    for (int i = tid; i < 4000; i += 256) {
        int tp = i / 40, j = i % 40;
        float acc = bs[j];
        #pragma unroll
        for (int c0 = 0; c0 < 64; c0++)
            acc = fmaf(xs[c0 * 100 + tp], ws[j * 65 + c0], acc);
        g_xproj[(b * 100 + tp) * 40 + j] = acc;
    }
}

// ---------------- K2: LSTM scan, chunked with contraction lead-in ----------------
// 100 blocks, 1 warp each: block b covers kept steps [b*512, b*512+512) with a
// 128-step lead-in from (h,c)=0 (error < 1e-20 by contraction).
__global__ void k_lstm(const float* __restrict__ whh) {
    const int lane = threadIdx.x;
    const int k = lane < 10 ? lane : 0;
    float wi[10], wf[10], wg[10], wo[10];
    #pragma unroll
    for (int m = 0; m < 10; m++) {
        wi[m] = whh[k * 10 + m];         wf[m] = whh[(k + 10) * 10 + m];
        wg[m] = whh[(k + 20) * 10 + m];  wo[m] = whh[(k + 30) * 10 + m];
    }
    const int t1 = blockIdx.x * CHL;
    const int t2 = t1 + CHL;
    int t0 = t1 - LEADL; if (t0 < 0) t0 = 0;

    float h[10];
    #pragma unroll
    for (int m = 0; m < 10; m++) h[m] = 0.f;
    float c = 0.f;
    const float* xp = g_xproj;
    float A[4], B[4];

#define LOAD4(S, t) { const float* p = xp + (size_t)(t) * 40 + k; \
    S[0] = p[0]; S[1] = p[10]; S[2] = p[20]; S[3] = p[30]; }

#define STEP(S, tc) { int tp = (tc) + 2; if (tp > NSTEP - 1) tp = NSTEP - 1; \
    float ai = S[0], af = S[1], ag = S[2], ao = S[3]; \
    LOAD4(S, tp); \
    _Pragma("unroll") \
    for (int m = 0; m < 10; m++) { \
        ai = fmaf(wi[m], h[m], ai); af = fmaf(wf[m], h[m], af); \
        ag = fmaf(wg[m], h[m], ag); ao = fmaf(wo[m], h[m], ao); } \
    float tg = tfast(ag); \
    c = fmaf(sigf(af), c, sigf(ai) * tg); \
    float hk = sigf(ao) * tfast(c); \
    if (lane < 10 && (tc) >= t1) g_hseq[(size_t)(tc) * 10 + lane] = hk; \
    _Pragma("unroll") \
    for (int m = 0; m < 10; m++) h[m] = __shfl_sync(0xffffffffu, hk, m); }

    LOAD4(A, t0); LOAD4(B, t0 + 1);
    for (int t = t0; t < t2; t += 2) {
        STEP(A, t);
        STEP(B, t + 1);
    }
#undef STEP
#undef LOAD4
}

// ---------------- K3: conv_out = hseq @ sc_w.T + sc_b ----------------
__global__ void k_sc(const float* __restrict__ scw, const float* __restrict__ scb) {
    int i = blockIdx.x * 256 + threadIdx.x;
    if (i >= NSTEP * 20) return;
    int r = i / 20, o = i % 20;
    float acc = scb[o];
    const float* hr = g_hseq + (size_t)r * 10;
    const float* w  = scw + o * 10;
    #pragma unroll
    for (int m = 0; m < 10; m++) acc = fmaf(hr[m], w[m], acc);
    g_xin1[i] = acc;
}

// ---------------- K4: 3-tau LIF scan, chunked (blocks over time chunks) ----------------
__global__ void k_lif3(int sel) {
    int l = threadIdx.x;
    if (l >= 60) return;
    int kk = l / 20, f = l % 20;
    const float* in = sel ? g_out1 : g_xin1;
    float tau = (kk == 0) ? 1.2231301601484298f
              : (kk == 1) ? 1.3678794411714423f : 1.4493289641172216f;
    float th  = (kk == 0) ? 0.14f : (kk == 1) ? 0.08f : 0.06f;
    float invt = 1.0f / tau, om = 1.0f - invt;

    const int t1 = blockIdx.x * CHF, t2 = t1 + CHF;
    int t0 = t1 - LEADF; if (t0 < 0) t0 = 0;
    const int n = t2 - t0, wskip = t1 - t0;
    const float* ip = in + (size_t)t0 * 20 + f;
    float* op = g_hl + (size_t)t0 * 60 + f * 3 + kk;

    float v = 0.f;
    float xr[16];
    #pragma unroll
    for (int u = 0; u < 16; u++) xr[u] = fmaf(ip[u * 20], invt, -th);
    for (int tb = 0; tb < n; tb += 16) {
        #pragma unroll
        for (int u = 0; u < 16; u++) {
            int t = tb + u;
            float d = fmaf(v, om, xr[u]);
            int np = t + 16;
            float nx = (np < n) ? ip[(size_t)np * 20] : 0.f;
            xr[u] = fmaf(nx, invt, -th);
            int msk = __float_as_int(d) >> 31;
            if (t >= wskip) op[(size_t)t * 60] = __int_as_float(~msk & 0x3f800000);
            v = __int_as_float(__float_as_int(d + th) & msk);
        }
    }
}

// ---------------- K5: c[t,o] = hl[t,:60] . conv_w[o,:60] + b[o] ----------------
__global__ void k_conv(const float* __restrict__ cw, const float* __restrict__ cb) {
    int i = blockIdx.x * 256 + threadIdx.x;
    if (i >= NSTEP * 20) return;
    int r = i / 20, o = i % 20;
    float acc = cb[o];
    const float* h0 = g_hl + (size_t)r * 60;
    const float* w  = cw + o * 60;
    #pragma unroll
    for (int m = 0; m < 60; m++) acc = fmaf(h0[m], w[m], acc);
    g_c[i] = acc;
}

// ---------------- K6: single-tau LIF scan, chunked ----------------
__global__ void k_lif4() {
    int f = threadIdx.x;
    if (f >= 20) return;
    const float invt = 1.0f / 1.3678794411714423f;
    const float om = 1.0f - invt, th = 0.08f;

    const int t1 = blockIdx.x * CHF, t2 = t1 + CHF;
    int t0 = t1 - LEADF; if (t0 < 0) t0 = 0;
    const int n = t2 - t0, wskip = t1 - t0;
    const float* ip = g_c + (size_t)t0 * 20 + f;
    float* op = g_s4 + (size_t)t0 * 20 + f;

    float v = 0.f;
    float xr[16];
    #pragma unroll
    for (int u = 0; u < 16; u++) xr[u] = fmaf(ip[u * 20], invt, -th);
    for (int tb = 0; tb < n; tb += 16) {
        #pragma unroll
        for (int u = 0; u < 16; u++) {
            int t = tb + u;
            float d = fmaf(v, om, xr[u]);
            int np = t + 16;
            float nx = (np < n) ? ip[(size_t)np * 20] : 0.f;
            xr[u] = fmaf(nx, invt, -th);
            int msk = __float_as_int(d) >> 31;
            if (t >= wskip) op[(size_t)t * 20] = __int_as_float(~msk & 0x3f800000);
            v = __int_as_float(__float_as_int(d + th) & msk);
        }
    }
}

// ---------------- K7: out = s4 @ fc.T + fc_b + xin @ skip.T + skip_b ----------------
__global__ void k_fcskip(const float* __restrict__ fcw, const float* __restrict__ fcb,
                         const float* __restrict__ skw, const float* __restrict__ skb,
                         int which) {
    int Fout = which ? 10 : 20;
    int i = blockIdx.x * 256 + threadIdx.x;
    if (i >= NSTEP * Fout) return;
    int r = i / Fout, o = i % Fout;
    const float* xin = which ? g_out1 : g_xin1;
    float* out       = which ? g_out2 : g_out1;
    float acc = fcb[o] + skb[o];
    const float* s  = g_s4 + (size_t)r * 20;
    const float* xr = xin + (size_t)r * 20;
    const float* w1 = fcw + o * 20;
    const float* w2 = skw + o * 20;
    #pragma unroll
    for (int m = 0; m < 20; m++)
        acc = fmaf(s[m], w1[m], fmaf(xr[m], w2[m], acc));
    out[i] = acc;
}

// ---------------- K8: final LIF over batch axis (512 steps, 1000 chains) ----------------
__global__ void k_liff() {
    int idx = threadIdx.x;
    if (idx >= 1000) return;
    const float invt = 1.0f / 1.3678794411714423f;
    const float om = 1.0f - invt, th = 0.08f;
    float v = 0.f;
    float xr[8];
    #pragma unroll
    for (int i = 0; i < 8; i++) xr[i] = fmaf(g_out2[i * 1000 + idx], invt, -th);
    for (int b = 0; b < BATCH; b += 8) {
        #pragma unroll
        for (int u = 0; u < 8; u++) {
            float d = fmaf(v, om, xr[u]);
            int nb = b + u + 8;
            float nx = (nb < BATCH) ? g_out2[nb * 1000 + idx] : 0.f;
            xr[u] = fmaf(nx, invt, -th);
            int msk = __float_as_int(d) >> 31;
            g_sfin[(b + u) * 1000 + idx] = __int_as_float(~msk & 0x3f800000);
            v = __int_as_float(__float_as_int(d + th) & msk);
        }
    }
}

// ---------------- K9: dp / avg / fused + per-batch partial sums ----------------
__global__ void k_fused() {
    int b = blockIdx.x, m = threadIdx.x;
    float dp[10];
    float s1 = 0.f, s2 = 0.f;
    if (m < 20) {
        const float* sb = g_sfin + b * 1000;
        float avgm = 0.f;
        #pragma unroll
        for (int j = 0; j < 10; j++) {
            float a = sb[(5 * m + 3) * 10 + j] + sb[(5 * m + 4) * 10 + j]
                    - sb[(5 * m + 0) * 10 + j] - sb[(5 * m + 1) * 10 + j];
            dp[j] = 0.5f * a;
            avgm += dp[j];
        }
        avgm *= 0.1f;
        #pragma unroll
        for (int j = 0; j < 10; j++) {
            float fv = dp[j] * avgm;
            g_fused[b * 200 + j * 20 + m] = fv;
            s1 += fv; s2 += fv * fv;
        }
    }
    #pragma unroll
    for (int off = 16; off; off >>= 1) {
        s1 += __shfl_xor_sync(0xffffffffu, s1, off);
        s2 += __shfl_xor_sync(0xffffffffu, s2, off);
    }
    if (m == 0) { g_part[b * 2] = s1; g_part[b * 2 + 1] = s2; }
}

// ---------------- K10: global mean/var ----------------
__global__ void k_stats(const float* __restrict__ gamma, const float* __restrict__ beta) {
    int l = threadIdx.x;
    float s1 = 0.f, s2 = 0.f;
    for (int i = l; i < BATCH; i += 32) { s1 += g_part[2 * i]; s2 += g_part[2 * i + 1]; }
    #pragma unroll
    for (int off = 16; off; off >>= 1) {
        s1 += __shfl_xor_sync(0xffffffffu, s1, off);
        s2 += __shfl_xor_sync(0xffffffffu, s2, off);
    }
    if (l == 0) {
        float n = (float)(BATCH * 200);
        float mean = s1 / n;
        float var = s2 / n - mean * mean;
        float rstd = 1.f / sqrtf(var + 1e-5f);
        g_stats[0] = mean; g_stats[1] = rstd * gamma[0]; g_stats[2] = beta[0];
    }
}

// ---------------- K11: BN + classifier + log_softmax ----------------
__global__ void k_logits(const float* __restrict__ clsw, const float* __restrict__ clsb,
                         float* __restrict__ out) {
    int b = blockIdx.x, l = threadIdx.x;
    float mean = g_stats[0], ga = g_stats[1], be = g_stats[2];
    float a0 = 0.f, a1 = 0.f, a2 = 0.f;
    for (int n = l; n < 200; n += 32) {
        float bn = (g_fused[b * 200 + n] - mean) * ga + be;
        a0 = fmaf(bn, clsw[n], a0);
        a1 = fmaf(bn, clsw[200 + n], a1);
        a2 = fmaf(bn, clsw[400 + n], a2);
    }
    #pragma unroll
    for (int off = 16; off; off >>= 1) {
        a0 += __shfl_xor_sync(0xffffffffu, a0, off);
        a1 += __shfl_xor_sync(0xffffffffu, a1, off);
        a2 += __shfl_xor_sync(0xffffffffu, a2, off);
    }
    if (l == 0) {
        float l0 = a0 + clsb[0], l1 = a1 + clsb[1], l2 = a2 + clsb[2];
        float mx = fmaxf(l0, fmaxf(l1, l2));
        float e0 = expf(l0 - mx), e1 = expf(l1 - mx), e2 = expf(l2 - mx);
        float lse = logf(e0 + e1 + e2) + mx;
        out[b * 3 + 0] = l0 - lse;
        out[b * 3 + 1] = l1 - lse;
        out[b * 3 + 2] = l2 - lse;
    }
}

// ---------------- launch ----------------
extern "C" void kernel_launch(void* const* d_in, const int* in_sizes, int n_in,
                              void* d_out, int out_size) {
    const float* x   = (const float*)d_in[0];
    const float* wih = (const float*)d_in[1];
    const float* whh = (const float*)d_in[2];
    const float* bih = (const float*)d_in[3];
    const float* bhh = (const float*)d_in[4];
    const float* scw = (const float*)d_in[5];
    const float* scb = (const float*)d_in[6];
    const float* c1w = (const float*)d_in[7];
    const float* c1b = (const float*)d_in[8];
    const float* f1w = (const float*)d_in[9];
    const float* f1b = (const float*)d_in[10];
    const float* s1w = (const float*)d_in[11];
    const float* s1b = (const float*)d_in[12];
    const float* c2w = (const float*)d_in[13];
    const float* c2b = (const float*)d_in[14];
    const float* f2w = (const float*)d_in[15];
    const float* f2b = (const float*)d_in[16];
    const float* s2w = (const float*)d_in[17];
    const float* s2b = (const float*)d_in[18];
    const float* gam = (const float*)d_in[19];
    const float* bet = (const float*)d_in[20];
    const float* clw = (const float*)d_in[21];
    const float* clb = (const float*)d_in[22];
    float* out = (float*)d_out;

    k_xproj <<<512, 256>>>(x, wih, bih, bhh);
    k_lstm  <<<NCHL, 32>>>(whh);
    k_sc    <<<4000, 256>>>(scw, scb);
    k_lif3  <<<NCHF, 64>>>(0);
    k_conv  <<<4000, 256>>>(c1w, c1b);
    k_lif4  <<<NCHF, 32>>>();
    k_fcskip<<<4000, 256>>>(f1w, f1b, s1w, s1b, 0);
    k_lif3  <<<NCHF, 64>>>(1);
    k_conv  <<<4000, 256>>>(c2w, c2b);
    k_lif4  <<<NCHF, 32>>>();
    k_fcskip<<<2000, 256>>>(f2w, f2b, s2w, s2b, 1);
    k_liff  <<<1, 1024>>>();
    k_fused <<<512, 32>>>();
    k_stats <<<1, 32>>>(gam, bet);
    k_logits<<<512, 32>>>(clw, clb, out);
}

// round 6
// speedup vs baseline: 51.7563x; 1.1083x over previous
#include <cuda_runtime.h>

#define NSTEP 51200
#define BATCH 512
// LSTM chunking
#define CHL   128
#define LEADL 128
#define NCHL  (NSTEP / CHL)
// HR-module chunking (fused kernel)
#define CHK   128          // kept steps per block
#define NCHK  (NSTEP / CHK)
#define RMAX  (CHK + 64)   // 32 lif3 lead + 32 lif4 lead

// ---------------- scratch (static device arrays; no allocation) ----------------
__device__ float g_xproj[NSTEP * 40];
__device__ float g_hseq [NSTEP * 10];
__device__ float g_out1 [NSTEP * 20];
__device__ float g_out2 [NSTEP * 10];
__device__ float g_sfin [NSTEP * 10];
__device__ float g_fused[BATCH * 200];
__device__ float g_part [BATCH * 2];
__device__ float g_stats[3];

__device__ __forceinline__ float sigf(float x)  { return __fdividef(1.f, 1.f + __expf(-x)); }
__device__ __forceinline__ float tfast(float x) { return __fdividef(2.f, 1.f + __expf(-2.f * x)) - 1.f; }

// ---------------- K1: LSTM input projection (fully parallel) ----------------
__global__ void k_xproj(const float* __restrict__ x, const float* __restrict__ wih,
                        const float* __restrict__ bih, const float* __restrict__ bhh) {
    __shared__ float xs[64 * 100];
    __shared__ float ws[40 * 65];
    __shared__ float bs[40];
    int b = blockIdx.x, tid = threadIdx.x;
    const float* xg = x + b * 6400;
    for (int i = tid; i < 6400; i += 256) xs[i] = xg[i];
    for (int i = tid; i < 2560; i += 256) ws[(i >> 6) * 65 + (i & 63)] = wih[i];
    if (tid < 40) bs[tid] = bih[tid] + bhh[tid];
    __syncthreads();
    for (int i = tid; i < 4000; i += 256) {
        int tp = i / 40, j = i % 40;
        float acc = bs[j];
        #pragma unroll
        for (int c0 = 0; c0 < 64; c0++)
            acc = fmaf(xs[c0 * 100 + tp], ws[j * 65 + c0], acc);
        g_xproj[(b * 100 + tp) * 40 + j] = acc;
    }
}

// ---------------- K2: LSTM scan, chunked with contraction lead-in ----------------
__global__ void k_lstm(const float* __restrict__ whh) {
    const int lane = threadIdx.x;
    const int k = lane < 10 ? lane : 0;
    float wi[10], wf[10], wg[10], wo[10];
    #pragma unroll
    for (int m = 0; m < 10; m++) {
        wi[m] = whh[k * 10 + m];         wf[m] = whh[(k + 10) * 10 + m];
        wg[m] = whh[(k + 20) * 10 + m];  wo[m] = whh[(k + 30) * 10 + m];
    }
    const int t1 = blockIdx.x * CHL;
    const int t2 = t1 + CHL;
    int t0 = t1 - LEADL; if (t0 < 0) t0 = 0;

    float h[10];
    #pragma unroll
    for (int m = 0; m < 10; m++) h[m] = 0.f;
    float c = 0.f;
    const float* xp = g_xproj;
    float A[4], B[4];

#define LOAD4(S, t) { const float* p = xp + (size_t)(t) * 40 + k; \
    S[0] = p[0]; S[1] = p[10]; S[2] = p[20]; S[3] = p[30]; }

#define STEP(S, tc) { int tp = (tc) + 2; if (tp > NSTEP - 1) tp = NSTEP - 1; \
    float ai = S[0], af = S[1], ag = S[2], ao = S[3]; \
    LOAD4(S, tp); \
    _Pragma("unroll") \
    for (int m = 0; m < 10; m++) { \
        ai = fmaf(wi[m], h[m], ai); af = fmaf(wf[m], h[m], af); \
        ag = fmaf(wg[m], h[m], ag); ao = fmaf(wo[m], h[m], ao); } \
    float tg = tfast(ag); \
    c = fmaf(sigf(af), c, sigf(ai) * tg); \
    float hk = sigf(ao) * tfast(c); \
    if (lane < 10 && (tc) >= t1) g_hseq[(size_t)(tc) * 10 + lane] = hk; \
    _Pragma("unroll") \
    for (int m = 0; m < 10; m++) h[m] = __shfl_sync(0xffffffffu, hk, m); }

    LOAD4(A, t0); LOAD4(B, t0 + 1);
    for (int t = t0; t < t2; t += 2) {
        STEP(A, t);
        STEP(B, t + 1);
    }
#undef STEP
#undef LOAD4
}

// ---------------- fc+skip inner body ----------------
template <int FOUT>
__device__ __forceinline__ void fcskip_row(const float* __restrict__ s4row,
                                           const float* __restrict__ xrow,
                                           const float* __restrict__ wfc,
                                           const float* __restrict__ wsk,
                                           const float* __restrict__ bb,
                                           float* __restrict__ orow) {
    float acc[FOUT];
    #pragma unroll
    for (int o = 0; o < FOUT; o++) acc[o] = bb[o];
    #pragma unroll
    for (int m = 0; m < 20; m++) {
        float sm = s4row[m], xm = xrow[m];
        #pragma unroll
        for (int o = 0; o < FOUT; o++)
            acc[o] = fmaf(sm, wfc[o * 20 + m], fmaf(xm, wsk[o * 20 + m], acc[o]));
    }
    #pragma unroll
    for (int o = 0; o < FOUT; o++) orow[o] = acc[o];
}

// ---------------- K3: fused HR module (sc/copy -> lif3 -> conv -> lif4 -> fc+skip) ----
__global__ void __launch_bounds__(256, 2)
k_hr(int which,
     const float* __restrict__ scw, const float* __restrict__ scb,
     const float* __restrict__ cw,  const float* __restrict__ cb,
     const float* __restrict__ fw,  const float* __restrict__ fb,
     const float* __restrict__ skw, const float* __restrict__ skb) {
    extern __shared__ float sm[];
    float* sx  = sm;                 // [RMAX][20] xin
    float* shl = sm + RMAX * 20;     // [RMAX][60] lif3 spikes
    float* sc4 = sm + RMAX * 80;     // [RMAX][20] conv out, overwritten by s4

    __shared__ float w_cv[1200], w_fc[400], w_sk[400], w_sc[200];
    __shared__ float b_cv[20], b_fs[20], b_sc[20];

    const int tid = threadIdx.x;
    const int FOUT = which ? 10 : 20;
    for (int i = tid; i < 1200; i += 256) w_cv[i] = cw[i];
    for (int i = tid; i < FOUT * 20; i += 256) { w_fc[i] = fw[i]; w_sk[i] = skw[i]; }
    if (!which) for (int i = tid; i < 200; i += 256) w_sc[i] = scw[i];
    if (tid < 20) { b_cv[tid] = cb[tid]; if (!which) b_sc[tid] = scb[tid]; }
    if (tid < FOUT) b_fs[tid] = fb[tid] + skb[tid];
    __syncthreads();          // <-- fix: weights/biases visible before stage A

    const int t1 = blockIdx.x * CHK;
    int t0 = t1 - 64; if (t0 < 0) t0 = 0;
    const int R = t1 + CHK - t0;
    const int rconv = (t1 >= 32 ? t1 - 32 : 0) - t0;   // 32 (or 0 for block 0)
    const int rkeep = t1 - t0;                         // 64 (or 0 for block 0)

    // ---- stage A: xin ----
    if (which == 0) {
        for (int i = tid; i < R * 20; i += 256) {
            int r = i / 20, o = i % 20;
            float acc = b_sc[o];
            const float* hr = g_hseq + (size_t)(t0 + r) * 10;
            #pragma unroll
            for (int m = 0; m < 10; m++) acc = fmaf(hr[m], w_sc[o * 10 + m], acc);
            sx[i] = acc;
        }
    } else {
        const float* src = g_out1 + (size_t)t0 * 20;
        for (int i = tid; i < R * 20; i += 256) sx[i] = src[i];
    }
    __syncthreads();

    // ---- stage B: lif3 (60 serial chains) ----
    if (tid < 60) {
        int kk = tid / 20, f = tid % 20;
        float tau = (kk == 0) ? 1.2231301601484298f
                  : (kk == 1) ? 1.3678794411714423f : 1.4493289641172216f;
        float th  = (kk == 0) ? 0.14f : (kk == 1) ? 0.08f : 0.06f;
        float invt = 1.0f / tau, om = 1.0f - invt;
        float v = 0.f;
        float* op = shl + f * 3 + kk;
        #pragma unroll 4
        for (int r = 0; r < R; r++) {
            float d = fmaf(v, om, fmaf(sx[r * 20 + f], invt, -th));
            int msk = __float_as_int(d) >> 31;
            op[r * 60] = __int_as_float(~msk & 0x3f800000);
            v = __int_as_float(__float_as_int(d + th) & msk);
        }
    }
    __syncthreads();

    // ---- stage C: conv (rows [rconv,R), half-rows per task) ----
    {
        int ntask = (R - rconv) * 2;
        for (int task = tid; task < ntask; task += 256) {
            int r = rconv + (task >> 1);
            int ob = (task & 1) * 10;
            float acc[10];
            #pragma unroll
            for (int o = 0; o < 10; o++) acc[o] = b_cv[ob + o];
            const float4* hrow = (const float4*)(shl + r * 60);
            #pragma unroll
            for (int mb = 0; mb < 15; mb++) {
                float4 hv = hrow[mb];
                #pragma unroll
                for (int o = 0; o < 10; o++) {
                    const float4 wv = *(const float4*)(w_cv + (ob + o) * 60 + mb * 4);
                    acc[o] = fmaf(hv.x, wv.x, acc[o]);
                    acc[o] = fmaf(hv.y, wv.y, acc[o]);
                    acc[o] = fmaf(hv.z, wv.z, acc[o]);
                    acc[o] = fmaf(hv.w, wv.w, acc[o]);
                }
            }
            #pragma unroll
            for (int o = 0; o < 10; o++) sc4[r * 20 + ob + o] = acc[o];
        }
    }
    __syncthreads();

    // ---- stage D: lif4 (20 serial chains), s4 overwrites c in place ----
    if (tid < 20) {
        const float invt = 1.0f / 1.3678794411714423f;
        const float om = 1.0f - invt, th = 0.08f;
        float v = 0.f;
        #pragma unroll 4
        for (int r = rconv; r < R; r++) {
            float d = fmaf(v, om, fmaf(sc4[r * 20 + tid], invt, -th));
            int msk = __float_as_int(d) >> 31;
            sc4[r * 20 + tid] = __int_as_float(~msk & 0x3f800000);
            v = __int_as_float(__float_as_int(d + th) & msk);
        }
    }
    __syncthreads();

    // ---- stage E: fc + skip on keep rows ----
    {
        int r = rkeep + tid;
        if (r < R) {
            if (which == 0)
                fcskip_row<20>(sc4 + r * 20, sx + r * 20, w_fc, w_sk, b_fs,
                               g_out1 + (size_t)(t0 + r) * 20);
            else
                fcskip_row<10>(sc4 + r * 20, sx + r * 20, w_fc, w_sk, b_fs,
                               g_out2 + (size_t)(t0 + r) * 10);
        }
    }
}

// ---------------- K4: final LIF over batch axis, chunked ----------------
__global__ void k_liff() {
    int idx = threadIdx.x;
    if (idx >= 1000) return;
    const float invt = 1.0f / 1.3678794411714423f;
    const float om = 1.0f - invt, th = 0.08f;
    const int b1 = blockIdx.x * 128, b2 = b1 + 128;
    int b0 = b1 - 48; if (b0 < 0) b0 = 0;
    float v = 0.f;
    for (int b = b0; b < b2; b++) {
        float d = fmaf(v, om, fmaf(g_out2[(size_t)b * 1000 + idx], invt, -th));
        int msk = __float_as_int(d) >> 31;
        if (b >= b1) g_sfin[(size_t)b * 1000 + idx] = __int_as_float(~msk & 0x3f800000);
        v = __int_as_float(__float_as_int(d + th) & msk);
    }
}

// ---------------- K5: dp / avg / fused + per-batch partial sums ----------------
__global__ void k_fused() {
    int b = blockIdx.x, m = threadIdx.x;
    float dp[10];
    float s1 = 0.f, s2 = 0.f;
    if (m < 20) {
        const float* sb = g_sfin + b * 1000;
        float avgm = 0.f;
        #pragma unroll
        for (int j = 0; j < 10; j++) {
            float a = sb[(5 * m + 3) * 10 + j] + sb[(5 * m + 4) * 10 + j]
                    - sb[(5 * m + 0) * 10 + j] - sb[(5 * m + 1) * 10 + j];
            dp[j] = 0.5f * a;
            avgm += dp[j];
        }
        avgm *= 0.1f;
        #pragma unroll
        for (int j = 0; j < 10; j++) {
            float fv = dp[j] * avgm;
            g_fused[b * 200 + j * 20 + m] = fv;
            s1 += fv; s2 += fv * fv;
        }
    }
    #pragma unroll
    for (int off = 16; off; off >>= 1) {
        s1 += __shfl_xor_sync(0xffffffffu, s1, off);
        s2 += __shfl_xor_sync(0xffffffffu, s2, off);
    }
    if (m == 0) { g_part[b * 2] = s1; g_part[b * 2 + 1] = s2; }
}

// ---------------- K6: global mean/var ----------------
__global__ void k_stats(const float* __restrict__ gamma, const float* __restrict__ beta) {
    int l = threadIdx.x;
    float s1 = 0.f, s2 = 0.f;
    for (int i = l; i < BATCH; i += 32) { s1 += g_part[2 * i]; s2 += g_part[2 * i + 1]; }
    #pragma unroll
    for (int off = 16; off; off >>= 1) {
        s1 += __shfl_xor_sync(0xffffffffu, s1, off);
        s2 += __shfl_xor_sync(0xffffffffu, s2, off);
    }
    if (l == 0) {
        float n = (float)(BATCH * 200);
        float mean = s1 / n;
        float var = s2 / n - mean * mean;
        float rstd = 1.f / sqrtf(var + 1e-5f);
        g_stats[0] = mean; g_stats[1] = rstd * gamma[0]; g_stats[2] = beta[0];
    }
}

// ---------------- K7: BN + classifier + log_softmax ----------------
__global__ void k_logits(const float* __restrict__ clsw, const float* __restrict__ clsb,
                         float* __restrict__ out) {
    int b = blockIdx.x, l = threadIdx.x;
    float mean = g_stats[0], ga = g_stats[1], be = g_stats[2];
    float a0 = 0.f, a1 = 0.f, a2 = 0.f;
    for (int n = l; n < 200; n += 32) {
        float bn = (g_fused[b * 200 + n] - mean) * ga + be;
        a0 = fmaf(bn, clsw[n], a0);
        a1 = fmaf(bn, clsw[200 + n], a1);
        a2 = fmaf(bn, clsw[400 + n], a2);
    }
    #pragma unroll
    for (int off = 16; off; off >>= 1) {
        a0 += __shfl_xor_sync(0xffffffffu, a0, off);
        a1 += __shfl_xor_sync(0xffffffffu, a1, off);
        a2 += __shfl_xor_sync(0xffffffffu, a2, off);
    }
    if (l == 0) {
        float l0 = a0 + clsb[0], l1 = a1 + clsb[1], l2 = a2 + clsb[2];
        float mx = fmaxf(l0, fmaxf(l1, l2));
        float e0 = expf(l0 - mx), e1 = expf(l1 - mx), e2 = expf(l2 - mx);
        float lse = logf(e0 + e1 + e2) + mx;
        out[b * 3 + 0] = l0 - lse;
        out[b * 3 + 1] = l1 - lse;
        out[b * 3 + 2] = l2 - lse;
    }
}

// ---------------- launch ----------------
extern "C" void kernel_launch(void* const* d_in, const int* in_sizes, int n_in,
                              void* d_out, int out_size) {
    const float* x   = (const float*)d_in[0];
    const float* wih = (const float*)d_in[1];
    const float* whh = (const float*)d_in[2];
    const float* bih = (const float*)d_in[3];
    const float* bhh = (const float*)d_in[4];
    const float* scw = (const float*)d_in[5];
    const float* scb = (const float*)d_in[6];
    const float* c1w = (const float*)d_in[7];
    const float* c1b = (const float*)d_in[8];
    const float* f1w = (const float*)d_in[9];
    const float* f1b = (const float*)d_in[10];
    const float* s1w = (const float*)d_in[11];
    const float* s1b = (const float*)d_in[12];
    const float* c2w = (const float*)d_in[13];
    const float* c2b = (const float*)d_in[14];
    const float* f2w = (const float*)d_in[15];
    const float* f2b = (const float*)d_in[16];
    const float* s2w = (const float*)d_in[17];
    const float* s2b = (const float*)d_in[18];
    const float* gam = (const float*)d_in[19];
    const float* bet = (const float*)d_in[20];
    const float* clw = (const float*)d_in[21];
    const float* clb = (const float*)d_in[22];
    float* out = (float*)d_out;

    static int smem_set = 0;
    const int HR_SMEM = RMAX * 100 * sizeof(float);   // 76.8 KB
    if (!smem_set) {
        cudaFuncSetAttribute(k_hr, cudaFuncAttributeMaxDynamicSharedMemorySize, HR_SMEM);
        smem_set = 1;
    }

    k_xproj <<<512, 256>>>(x, wih, bih, bhh);
    k_lstm  <<<NCHL, 32>>>(whh);
    k_hr    <<<NCHK, 256, HR_SMEM>>>(0, scw, scb, c1w, c1b, f1w, f1b, s1w, s1b);
    k_hr    <<<NCHK, 256, HR_SMEM>>>(1, scw, scb, c2w, c2b, f2w, f2b, s2w, s2b);
    k_liff  <<<4, 1024>>>();
    k_fused <<<512, 32>>>();
    k_stats <<<1, 32>>>(gam, bet);
    k_logits<<<512, 32>>>(clw, clb, out);
}

// round 7
// speedup vs baseline: 97.3711x; 1.8813x over previous
#include <cuda_runtime.h>

#define NSTEP 51200
#define BATCH 512
// LSTM chunking
#define CHL   64
#define LEADL 96
#define NCHL  (NSTEP / CHL)
// HR-module chunking (fused kernel)
#define CHK   128          // kept steps per block
#define NCHK  (NSTEP / CHK)
#define RMAX  (CHK + 64)   // 32 lif3 lead + 32 lif4 lead

// ---------------- scratch (static device arrays; no allocation) ----------------
__device__ float g_xproj[NSTEP * 40];
__device__ float g_hseq [NSTEP * 10];
__device__ float g_out1 [NSTEP * 20];
__device__ float g_out2 [NSTEP * 10];
__device__ float g_sfin [NSTEP * 10];
__device__ float g_fused[BATCH * 200];
__device__ float g_part [BATCH * 2];
__device__ float g_stats[3];

__device__ __forceinline__ float sigf(float x)  { return __fdividef(1.f, 1.f + __expf(-x)); }
__device__ __forceinline__ float tfast(float x) { return __fdividef(2.f, 1.f + __expf(-2.f * x)) - 1.f; }

// packed f32x2 helpers (Blackwell FFMA2; IEEE-exact per component)
__device__ __forceinline__ unsigned long long pk2(float a, float b) {
    unsigned long long r; asm("mov.b64 %0, {%1, %2};" : "=l"(r) : "f"(a), "f"(b)); return r;
}
__device__ __forceinline__ unsigned long long fma2(unsigned long long a, unsigned long long b,
                                                   unsigned long long c) {
    unsigned long long d;
    asm("fma.rn.f32x2 %0, %1, %2, %3;" : "=l"(d) : "l"(a), "l"(b), "l"(c)); return d;
}
__device__ __forceinline__ void upk2(unsigned long long v, float& lo, float& hi) {
    asm("mov.b64 {%0, %1}, %2;" : "=f"(lo), "=f"(hi) : "l"(v));
}

// ---------------- K1: LSTM input projection (fully parallel) ----------------
__global__ void k_xproj(const float* __restrict__ x, const float* __restrict__ wih,
                        const float* __restrict__ bih, const float* __restrict__ bhh) {
    __shared__ float xs[64 * 100];
    __shared__ float ws[40 * 65];
    __shared__ float bs[40];
    int b = blockIdx.x, tid = threadIdx.x;
    const float* xg = x + b * 6400;
    for (int i = tid; i < 6400; i += 256) xs[i] = xg[i];
    for (int i = tid; i < 2560; i += 256) ws[(i >> 6) * 65 + (i & 63)] = wih[i];
    if (tid < 40) bs[tid] = bih[tid] + bhh[tid];
    __syncthreads();
    for (int i = tid; i < 4000; i += 256) {
        int tp = i / 40, j = i % 40;
        float acc = bs[j];
        #pragma unroll
        for (int c0 = 0; c0 < 64; c0++)
            acc = fmaf(xs[c0 * 100 + tp], ws[j * 65 + c0], acc);
        g_xproj[(b * 100 + tp) * 40 + j] = acc;
    }
}

// ---------------- K2: LSTM scan, chunked, FFMA2-packed gate dot-products ----------
__global__ void k_lstm(const float* __restrict__ whh) {
    const int lane = threadIdx.x;
    const int k = lane < 10 ? lane : 0;
    unsigned long long wif[10], wgo[10];
    #pragma unroll
    for (int m = 0; m < 10; m++) {
        wif[m] = pk2(whh[k * 10 + m],        whh[(k + 10) * 10 + m]);
        wgo[m] = pk2(whh[(k + 20) * 10 + m], whh[(k + 30) * 10 + m]);
    }
    const int t1 = blockIdx.x * CHL;
    const int t2 = t1 + CHL;
    int t0 = t1 - LEADL; if (t0 < 0) t0 = 0;

    unsigned long long hh[10];
    #pragma unroll
    for (int m = 0; m < 10; m++) hh[m] = 0ull;
    float c = 0.f;
    const float* xp = g_xproj;
    float A[4], B[4];

#define LOAD4(S, t) { const float* p = xp + (size_t)(t) * 40 + k; \
    S[0] = p[0]; S[1] = p[10]; S[2] = p[20]; S[3] = p[30]; }

#define STEP(S, tc) { int tp = (tc) + 2; if (tp > NSTEP - 1) tp = NSTEP - 1; \
    unsigned long long aif = pk2(S[0], S[1]), ago = pk2(S[2], S[3]); \
    LOAD4(S, tp); \
    _Pragma("unroll") \
    for (int m = 0; m < 10; m++) { \
        aif = fma2(wif[m], hh[m], aif); ago = fma2(wgo[m], hh[m], ago); } \
    float ai, af, ag, ao; upk2(aif, ai, af); upk2(ago, ag, ao); \
    float tg = tfast(ag); \
    c = fmaf(sigf(af), c, sigf(ai) * tg); \
    float hk = sigf(ao) * tfast(c); \
    if (lane < 10 && (tc) >= t1) g_hseq[(size_t)(tc) * 10 + lane] = hk; \
    _Pragma("unroll") \
    for (int m = 0; m < 10; m++) { \
        float hm = __shfl_sync(0xffffffffu, hk, m); hh[m] = pk2(hm, hm); } }

    LOAD4(A, t0); LOAD4(B, t0 + 1);
    for (int t = t0; t < t2; t += 2) {
        STEP(A, t);
        STEP(B, t + 1);
    }
#undef STEP
#undef LOAD4
}

// ---------------- fc+skip inner body ----------------
template <int FOUT>
__device__ __forceinline__ void fcskip_row(const float* __restrict__ s4row,
                                           const float* __restrict__ xrow,
                                           const float* __restrict__ wfc,
                                           const float* __restrict__ wsk,
                                           const float* __restrict__ bb,
                                           float* __restrict__ orow) {
    float acc[FOUT];
    #pragma unroll
    for (int o = 0; o < FOUT; o++) acc[o] = bb[o];
    #pragma unroll
    for (int m = 0; m < 20; m++) {
        float sm = s4row[m], xm = xrow[m];
        #pragma unroll
        for (int o = 0; o < FOUT; o++)
            acc[o] = fmaf(sm, wfc[o * 20 + m], fmaf(xm, wsk[o * 20 + m], acc[o]));
    }
    #pragma unroll
    for (int o = 0; o < FOUT; o++) orow[o] = acc[o];
}

// ---------------- K3: fused HR module (templated: one instantiation per launch) ----
template <int WHICH>
__global__ void __launch_bounds__(256, 2)
k_hr(const float* __restrict__ scw, const float* __restrict__ scb,
     const float* __restrict__ cw,  const float* __restrict__ cb,
     const float* __restrict__ fw,  const float* __restrict__ fb,
     const float* __restrict__ skw, const float* __restrict__ skb) {
    extern __shared__ float sm[];
    float* sx  = sm;                 // [RMAX][20] xin
    float* shl = sm + RMAX * 20;     // [RMAX][60] lif3 spikes
    float* sc4 = sm + RMAX * 80;     // [RMAX][20] staging / conv out / s4

    constexpr int FOUT = WHICH ? 10 : 20;
    __shared__ float w_cv[1200], w_fc[FOUT * 20], w_sk[FOUT * 20], w_sc[200];
    __shared__ float b_cv[20], b_fs[FOUT], b_sc[20];

    const int tid = threadIdx.x;
    for (int i = tid; i < 1200; i += 256) w_cv[i] = cw[i];
    for (int i = tid; i < FOUT * 20; i += 256) { w_fc[i] = fw[i]; w_sk[i] = skw[i]; }
    if (WHICH == 0) for (int i = tid; i < 200; i += 256) w_sc[i] = scw[i];
    if (tid < 20) { b_cv[tid] = cb[tid]; if (WHICH == 0) b_sc[tid] = scb[tid]; }
    if (tid < FOUT) b_fs[tid] = fb[tid] + skb[tid];

    const int t1 = blockIdx.x * CHK;
    int t0 = t1 - 64; if (t0 < 0) t0 = 0;
    const int R = t1 + CHK - t0;
    const int rconv = (t1 >= 32 ? t1 - 32 : 0) - t0;   // 32 (or 0 for block 0)
    const int rkeep = t1 - t0;                         // 64 (or 0 for block 0)

    // ---- stage A: xin into sx ----
    if (WHICH == 0) {
        // stage hseq chunk into sc4 (coalesced float4), then small matmul from smem
        {
            const float4* h4 = (const float4*)(g_hseq + (size_t)t0 * 10);
            float4* d4 = (float4*)sc4;
            const int n4 = (R * 10) >> 2;
            for (int i = tid; i < n4; i += 256) d4[i] = h4[i];
        }
        __syncthreads();
        for (int i = tid; i < R * 20; i += 256) {
            int r = i / 20, o = i % 20;
            float acc = b_sc[o];
            const float* hr = sc4 + r * 10;
            #pragma unroll
            for (int m = 0; m < 10; m++) acc = fmaf(hr[m], w_sc[o * 10 + m], acc);
            sx[i] = acc;
        }
    } else {
        const float4* s4p = (const float4*)(g_out1 + (size_t)t0 * 20);
        float4* d4 = (float4*)sx;
        const int n4 = (R * 20) >> 2;
        for (int i = tid; i < n4; i += 256) d4[i] = s4p[i];
    }
    __syncthreads();

    // ---- stage B: lif3 (60 serial chains) ----
    if (tid < 60) {
        int kk = tid / 20, f = tid % 20;
        float tau = (kk == 0) ? 1.2231301601484298f
                  : (kk == 1) ? 1.3678794411714423f : 1.4493289641172216f;
        float th  = (kk == 0) ? 0.14f : (kk == 1) ? 0.08f : 0.06f;
        float invt = 1.0f / tau, om = 1.0f - invt;
        float v = 0.f;
        float* op = shl + f * 3 + kk;
        #pragma unroll 2
        for (int r = 0; r < R; r++) {
            float d = fmaf(v, om, fmaf(sx[r * 20 + f], invt, -th));
            int msk = __float_as_int(d) >> 31;
            op[r * 60] = __int_as_float(~msk & 0x3f800000);
            v = __int_as_float(__float_as_int(d + th) & msk);
        }
    }
    __syncthreads();

    // ---- stage C: conv (rows [rconv,R)); warp-uniform output half (wv broadcast) ----
    {
        const int nrows = R - rconv;          // 160, or 128 for block 0 (mult of 32)
        const int ntask = nrows * 2;
        for (int task = tid; task < ntask; task += 256) {
            int r, ob;
            if (task < nrows) { r = rconv + task;         ob = 0;  }
            else              { r = rconv + task - nrows; ob = 10; }
            float acc[10];
            #pragma unroll
            for (int o = 0; o < 10; o++) acc[o] = b_cv[ob + o];
            const float4* hrow = (const float4*)(shl + r * 60);
            #pragma unroll
            for (int mb = 0; mb < 15; mb++) {
                float4 hv = hrow[mb];
                #pragma unroll
                for (int o = 0; o < 10; o++) {
                    const float4 wv = *(const float4*)(w_cv + (ob + o) * 60 + mb * 4);
                    acc[o] = fmaf(hv.x, wv.x, acc[o]);
                    acc[o] = fmaf(hv.y, wv.y, acc[o]);
                    acc[o] = fmaf(hv.z, wv.z, acc[o]);
                    acc[o] = fmaf(hv.w, wv.w, acc[o]);
                }
            }
            #pragma unroll
            for (int o = 0; o < 10; o++) sc4[r * 20 + ob + o] = acc[o];
        }
    }
    __syncthreads();

    // ---- stage D: lif4 (20 serial chains), s4 overwrites c in place ----
    if (tid < 20) {
        const float invt = 1.0f / 1.3678794411714423f;
        const float om = 1.0f - invt, th = 0.08f;
        float v = 0.f;
        #pragma unroll 2
        for (int r = rconv; r < R; r++) {
            float d = fmaf(v, om, fmaf(sc4[r * 20 + tid], invt, -th));
            int msk = __float_as_int(d) >> 31;
            sc4[r * 20 + tid] = __int_as_float(~msk & 0x3f800000);
            v = __int_as_float(__float_as_int(d + th) & msk);
        }
    }
    __syncthreads();

    // ---- stage E: fc + skip on keep rows ----
    {
        int r = rkeep + tid;
        if (r < R) {
            if (WHICH == 0)
                fcskip_row<20>(sc4 + r * 20, sx + r * 20, w_fc, w_sk, b_fs,
                               g_out1 + (size_t)(t0 + r) * 20);
            else
                fcskip_row<10>(sc4 + r * 20, sx + r * 20, w_fc, w_sk, b_fs,
                               g_out2 + (size_t)(t0 + r) * 10);
        }
    }
}

// ---------------- K4: final LIF over batch axis, chunked ----------------
__global__ void k_liff() {
    int idx = threadIdx.x;
    if (idx >= 1000) return;
    const float invt = 1.0f / 1.3678794411714423f;
    const float om = 1.0f - invt, th = 0.08f;
    const int b1 = blockIdx.x * 128, b2 = b1 + 128;
    int b0 = b1 - 48; if (b0 < 0) b0 = 0;
    float v = 0.f;
    for (int b = b0; b < b2; b++) {
        float d = fmaf(v, om, fmaf(g_out2[(size_t)b * 1000 + idx], invt, -th));
        int msk = __float_as_int(d) >> 31;
        if (b >= b1) g_sfin[(size_t)b * 1000 + idx] = __int_as_float(~msk & 0x3f800000);
        v = __int_as_float(__float_as_int(d + th) & msk);
    }
}

// ---------------- K5: dp / avg / fused + per-batch partial sums ----------------
__global__ void k_fused() {
    int b = blockIdx.x, m = threadIdx.x;
    float dp[10];
    float s1 = 0.f, s2 = 0.f;
    if (m < 20) {
        const float* sb = g_sfin + b * 1000;
        float avgm = 0.f;
        #pragma unroll
        for (int j = 0; j < 10; j++) {
            float a = sb[(5 * m + 3) * 10 + j] + sb[(5 * m + 4) * 10 + j]
                    - sb[(5 * m + 0) * 10 + j] - sb[(5 * m + 1) * 10 + j];
            dp[j] = 0.5f * a;
            avgm += dp[j];
        }
        avgm *= 0.1f;
        #pragma unroll
        for (int j = 0; j < 10; j++) {
            float fv = dp[j] * avgm;
            g_fused[b * 200 + j * 20 + m] = fv;
            s1 += fv; s2 += fv * fv;
        }
    }
    #pragma unroll
    for (int off = 16; off; off >>= 1) {
        s1 += __shfl_xor_sync(0xffffffffu, s1, off);
        s2 += __shfl_xor_sync(0xffffffffu, s2, off);
    }
    if (m == 0) { g_part[b * 2] = s1; g_part[b * 2 + 1] = s2; }
}

// ---------------- K6: global mean/var ----------------
__global__ void k_stats(const float* __restrict__ gamma, const float* __restrict__ beta) {
    int l = threadIdx.x;
    float s1 = 0.f, s2 = 0.f;
    for (int i = l; i < BATCH; i += 32) { s1 += g_part[2 * i]; s2 += g_part[2 * i + 1]; }
    #pragma unroll
    for (int off = 16; off; off >>= 1) {
        s1 += __shfl_xor_sync(0xffffffffu, s1, off);
        s2 += __shfl_xor_sync(0xffffffffu, s2, off);
    }
    if (l == 0) {
        float n = (float)(BATCH * 200);
        float mean = s1 / n;
        float var = s2 / n - mean * mean;
        float rstd = 1.f / sqrtf(var + 1e-5f);
        g_stats[0] = mean; g_stats[1] = rstd * gamma[0]; g_stats[2] = beta[0];
    }
}

// ---------------- K7: BN + classifier + log_softmax ----------------
__global__ void k_logits(const float* __restrict__ clsw, const float* __restrict__ clsb,
                         float* __restrict__ out) {
    int b = blockIdx.x, l = threadIdx.x;
    float mean = g_stats[0], ga = g_stats[1], be = g_stats[2];
    float a0 = 0.f, a1 = 0.f, a2 = 0.f;
    for (int n = l; n < 200; n += 32) {
        float bn = (g_fused[b * 200 + n] - mean) * ga + be;
        a0 = fmaf(bn, clsw[n], a0);
        a1 = fmaf(bn, clsw[200 + n], a1);
        a2 = fmaf(bn, clsw[400 + n], a2);
    }
    #pragma unroll
    for (int off = 16; off; off >>= 1) {
        a0 += __shfl_xor_sync(0xffffffffu, a0, off);
        a1 += __shfl_xor_sync(0xffffffffu, a1, off);
        a2 += __shfl_xor_sync(0xffffffffu, a2, off);
    }
    if (l == 0) {
        float l0 = a0 + clsb[0], l1 = a1 + clsb[1], l2 = a2 + clsb[2];
        float mx = fmaxf(l0, fmaxf(l1, l2));
        float e0 = expf(l0 - mx), e1 = expf(l1 - mx), e2 = expf(l2 - mx);
        float lse = logf(e0 + e1 + e2) + mx;
        out[b * 3 + 0] = l0 - lse;
        out[b * 3 + 1] = l1 - lse;
        out[b * 3 + 2] = l2 - lse;
    }
}

// ---------------- launch ----------------
extern "C" void kernel_launch(void* const* d_in, const int* in_sizes, int n_in,
                              void* d_out, int out_size) {
    const float* x   = (const float*)d_in[0];
    const float* wih = (const float*)d_in[1];
    const float* whh = (const float*)d_in[2];
    const float* bih = (const float*)d_in[3];
    const float* bhh = (const float*)d_in[4];
    const float* scw = (const float*)d_in[5];
    const float* scb = (const float*)d_in[6];
    const float* c1w = (const float*)d_in[7];
    const float* c1b = (const float*)d_in[8];
    const float* f1w = (const float*)d_in[9];
    const float* f1b = (const float*)d_in[10];
    const float* s1w = (const float*)d_in[11];
    const float* s1b = (const float*)d_in[12];
    const float* c2w = (const float*)d_in[13];
    const float* c2b = (const float*)d_in[14];
    const float* f2w = (const float*)d_in[15];
    const float* f2b = (const float*)d_in[16];
    const float* s2w = (const float*)d_in[17];
    const float* s2b = (const float*)d_in[18];
    const float* gam = (const float*)d_in[19];
    const float* bet = (const float*)d_in[20];
    const float* clw = (const float*)d_in[21];
    const float* clb = (const float*)d_in[22];
    float* out = (float*)d_out;

    static int smem_set = 0;
    const int HR_SMEM = RMAX * 100 * sizeof(float);   // 76.8 KB
    if (!smem_set) {
        cudaFuncSetAttribute(k_hr<0>, cudaFuncAttributeMaxDynamicSharedMemorySize, HR_SMEM);
        cudaFuncSetAttribute(k_hr<1>, cudaFuncAttributeMaxDynamicSharedMemorySize, HR_SMEM);
        smem_set = 1;
    }

    k_xproj <<<512, 256>>>(x, wih, bih, bhh);
    k_lstm  <<<NCHL, 32>>>(whh);
    k_hr<0> <<<NCHK, 256, HR_SMEM>>>(scw, scb, c1w, c1b, f1w, f1b, s1w, s1b);
    k_hr<1> <<<NCHK, 256, HR_SMEM>>>(scw, scb, c2w, c2b, f2w, f2b, s2w, s2b);
    k_liff  <<<4, 1024>>>();
    k_fused <<<512, 32>>>();
    k_stats <<<1, 32>>>(gam, bet);
    k_logits<<<512, 32>>>(clw, clb, out);
}